// round 5
// baseline (speedup 1.0000x reference)
#include <cuda_runtime.h>
#include <math.h>

#define HQ_  32
#define HKV_ 8
#define D_   64
#define HID_ 2048
#define B_   2
#define T_   2048
#define M_   (B_*T_)          // 4096 rows (B*T)
#define NQKV_ 3072            // 2048 (Q) + 512 (K) + 512 (V)

typedef unsigned long long ull;

// Packed f32x2 ops (sm_100+; FFMA2 path ptxas won't emit on its own).
// PACK/UNPACK use b32 ("r") operands to match ptxas's mov.b64 type rules
// (the ptx_helpers.cuh convention); float bits routed via __float_as_uint.
#define FMA_F32X2(d, a, b, c) \
    asm("fma.rn.f32x2 %0, %1, %2, %3;" : "=l"(d) : "l"(a), "l"(b), "l"(c))
#define MUL_F32X2(d, a, b) \
    asm("mul.rn.f32x2 %0, %1, %2;" : "=l"(d) : "l"(a), "l"(b))
#define PACK_F32X2(d, lo, hi) \
    asm("mov.b64 %0, {%1, %2};" : "=l"(d) \
        : "r"(__float_as_uint(lo)), "r"(__float_as_uint(hi)))
#define UNPACK_F32X2(lo, hi, s) do {                                   \
    unsigned _u0, _u1;                                                 \
    asm("mov.b64 {%0, %1}, %2;" : "=r"(_u0), "=r"(_u1) : "l"(s));      \
    (lo) = __uint_as_float(_u0); (hi) = __uint_as_float(_u1);          \
} while (0)

// Scratch (device globals; no runtime allocation allowed)
__device__ float g_QKV[(size_t)M_ * NQKV_];          // pre-rope QKV, (B*T, 3072)
__device__ float g_Q[(size_t)B_ * HQ_ * T_ * D_];    // (B, HQ, T, D)
__device__ float g_K[(size_t)B_ * HKV_ * T_ * D_];   // (B, HKV, T, D)
__device__ float g_V[(size_t)B_ * HKV_ * T_ * D_];   // (B, HKV, T, D)
__device__ float g_attn[(size_t)M_ * HQ_ * D_];      // (B*T, HQ*D)

// ---------------------------------------------------------------------------
// Core NT SGEMM tile: C[bm.., bnC..] = A[bm..,k] * W[bnW..,k]
// 128x128 tile, BK=8, 256 threads, 8x8 micro-tile (held as 8x4 f32x2 pairs),
// double-buffered smem (one __syncthreads per K-step).
// ---------------------------------------------------------------------------
__device__ __forceinline__ void sgemm_tile(
    const float* __restrict__ A, const float* __restrict__ W,
    float* __restrict__ C, int K, int ldc, int bm, int bnW, int bnC)
{
    __shared__ float As[2][8][132];   // +4 pad: conflict-free transposed stores
    __shared__ float Ws[2][8][132];
    const int tid  = threadIdx.x;
    const int lrow = tid >> 1;            // 0..127
    const int lcol = (tid & 1) << 2;      // 0 or 4
    const float* Ap = A + (size_t)(bm  + lrow) * K + lcol;
    const float* Wp = W + (size_t)(bnW + lrow) * K + lcol;
    const int trow = (tid >> 4) << 3;     // 0..120
    const int tcol = (tid & 15) << 3;     // 0..120

    ull acc2[8][4];                       // [row][col-pair], f32x2 packed
    #pragma unroll
    for (int i = 0; i < 8; i++)
        #pragma unroll
        for (int j = 0; j < 4; j++) acc2[i][j] = 0ull;  // {0.f,0.f}

    float4 av = *(const float4*)Ap;
    float4 wv = *(const float4*)Wp;

    // stage tile 0 into buffer 0
    As[0][lcol+0][lrow] = av.x; As[0][lcol+1][lrow] = av.y;
    As[0][lcol+2][lrow] = av.z; As[0][lcol+3][lrow] = av.w;
    Ws[0][lcol+0][lrow] = wv.x; Ws[0][lcol+1][lrow] = wv.y;
    Ws[0][lcol+2][lrow] = wv.z; Ws[0][lcol+3][lrow] = wv.w;
    __syncthreads();

    int buf = 0;
    for (int k0 = 0; k0 < K; k0 += 8) {
        const bool more = (k0 + 8 < K);
        if (more) {                       // prefetch next tile into regs
            av = *(const float4*)(Ap + k0 + 8);
            wv = *(const float4*)(Wp + k0 + 8);
        }
        #pragma unroll
        for (int kk = 0; kk < 8; kk++) {
            float4 a0 = *(const float4*)&As[buf][kk][trow];
            float4 a1 = *(const float4*)&As[buf][kk][trow+4];
            // W pairs are natural adjacent floats -> reinterpret as f32x2
            // (row base offset 132*4=528B and tcol*4 (32B-multiple) keep 16B align)
            ulonglong2 w01 = *(const ulonglong2*)&Ws[buf][kk][tcol];
            ulonglong2 w23 = *(const ulonglong2*)&Ws[buf][kk][tcol+4];
            const ull wp[4] = {w01.x, w01.y, w23.x, w23.y};
            const float a[8] = {a0.x,a0.y,a0.z,a0.w,a1.x,a1.y,a1.z,a1.w};
            #pragma unroll
            for (int i = 0; i < 8; i++) {
                ull aa; PACK_F32X2(aa, a[i], a[i]);   // broadcast pack (alu pipe)
                #pragma unroll
                for (int j = 0; j < 4; j++)
                    FMA_F32X2(acc2[i][j], aa, wp[j], acc2[i][j]);
            }
        }
        if (more) {                       // store into the other buffer
            const int nb = buf ^ 1;
            As[nb][lcol+0][lrow] = av.x; As[nb][lcol+1][lrow] = av.y;
            As[nb][lcol+2][lrow] = av.z; As[nb][lcol+3][lrow] = av.w;
            Ws[nb][lcol+0][lrow] = wv.x; Ws[nb][lcol+1][lrow] = wv.y;
            Ws[nb][lcol+2][lrow] = wv.z; Ws[nb][lcol+3][lrow] = wv.w;
            __syncthreads();
            buf = nb;
        }
    }

    float* Cp = C + (size_t)(bm + trow) * ldc + bnC + tcol;
    #pragma unroll
    for (int i = 0; i < 8; i++) {
        float c0,c1,c2,c3,c4,c5,c6,c7;
        UNPACK_F32X2(c0, c1, acc2[i][0]);
        UNPACK_F32X2(c2, c3, acc2[i][1]);
        UNPACK_F32X2(c4, c5, acc2[i][2]);
        UNPACK_F32X2(c6, c7, acc2[i][3]);
        *(float4*)(Cp + (size_t)i * ldc)     = make_float4(c0,c1,c2,c3);
        *(float4*)(Cp + (size_t)i * ldc + 4) = make_float4(c4,c5,c6,c7);
    }
}

// Fused QKV projection: one launch covers Q (cols 0..2047), K (2048..2559),
// V (2560..3071); the weight tensor is selected per-block from bn.
__global__ __launch_bounds__(256) void qkv_gemm(
    const float* __restrict__ hidden,
    const float* __restrict__ q_w, const float* __restrict__ k_w,
    const float* __restrict__ v_w, float* __restrict__ C)
{
    const int bn = blockIdx.x * 128;
    const float* W; int wrow;
    if (bn < 2048)      { W = q_w; wrow = bn; }
    else if (bn < 2560) { W = k_w; wrow = bn - 2048; }
    else                { W = v_w; wrow = bn - 2560; }
    sgemm_tile(hidden, W, C, HID_, NQKV_, blockIdx.y * 128, wrow, bn);
}

// Plain NT GEMM (output projection)
__global__ __launch_bounds__(256) void sgemm_nt(
    const float* __restrict__ A, const float* __restrict__ W,
    float* __restrict__ C, int K, int ldc)
{
    sgemm_tile(A, W, C, K, ldc, blockIdx.y * 128, blockIdx.x * 128, blockIdx.x * 128);
}

// ---------------------------------------------------------------------------
// Bias add + RoPE + layout transform.
// One block per token (B*T blocks). positions == arange(T) by construction.
// ---------------------------------------------------------------------------
__global__ __launch_bounds__(128) void rope_reshape(
    const float* __restrict__ qkv,
    const float* __restrict__ qb, const float* __restrict__ kb,
    const float* __restrict__ vb,
    float* __restrict__ Q, float* __restrict__ K, float* __restrict__ V)
{
    const int bt = blockIdx.x;
    const int b = bt / T_, t = bt % T_;
    const float* row = qkv + (size_t)bt * NQKV_;
    const float pos = (float)t;
    const float LOG_TH_OVER_HALF = 9.210340371976184f / 32.0f; // ln(10000)/(D/2)

    for (int it = threadIdx.x; it < HQ_*32; it += blockDim.x) {
        int h = it >> 5, j = it & 31;
        float invf = expf(-(float)j * LOG_TH_OVER_HALF);
        float sn, cs; sincosf(pos * invf, &sn, &cs);
        float x1 = row[h*64 + j]      + qb[h*64 + j];
        float x2 = row[h*64 + j + 32] + qb[h*64 + j + 32];
        float* o = Q + (((size_t)b*HQ_ + h)*T_ + t)*64;
        o[j]      = x1*cs - x2*sn;
        o[j + 32] = x2*cs + x1*sn;
    }
    for (int it = threadIdx.x; it < HKV_*32; it += blockDim.x) {
        int h = it >> 5, j = it & 31;
        float invf = expf(-(float)j * LOG_TH_OVER_HALF);
        float sn, cs; sincosf(pos * invf, &sn, &cs);
        float x1 = row[2048 + h*64 + j]      + kb[h*64 + j];
        float x2 = row[2048 + h*64 + j + 32] + kb[h*64 + j + 32];
        float* o = K + (((size_t)b*HKV_ + h)*T_ + t)*64;
        o[j]      = x1*cs - x2*sn;
        o[j + 32] = x2*cs + x1*sn;
    }
    for (int it = threadIdx.x; it < HKV_*64; it += blockDim.x) {
        V[(((size_t)b*HKV_ + (it >> 6))*T_ + t)*64 + (it & 63)] =
            row[2560 + it] + vb[it];
    }
}

// ---------------------------------------------------------------------------
// Flash-style causal GQA attention, chunked online softmax (8 keys/step),
// all heavy math in packed f32x2. Grid: (T/128, B*HQ), qt reversed. Block:
// 128 threads; thread i owns one query row. K/V in 64x64 smem tiles.
// ---------------------------------------------------------------------------
__global__ __launch_bounds__(128) void attn_kernel(
    const float* __restrict__ Q, const float* __restrict__ K,
    const float* __restrict__ V, float* __restrict__ O)
{
    const int qt = (gridDim.x - 1) - blockIdx.x;   // longest first
    const int bh = blockIdx.y;
    const int b = bh / HQ_, h = bh % HQ_;
    const int kvh = h / (HQ_ / HKV_);
    const float* Qp = Q + (((size_t)b*HQ_  + h  )*T_) * D_;
    const float* Kp = K + (((size_t)b*HKV_ + kvh)*T_) * D_;
    const float* Vp = V + (((size_t)b*HKV_ + kvh)*T_) * D_;
    const int i = qt*128 + threadIdx.x;            // my query row

    // q packed once: 32 f32x2 pairs, with 1/sqrt(D) folded in
    ull q2[32];
    {
        const float4* qr = (const float4*)(Qp + (size_t)i * D_);
        #pragma unroll
        for (int d4 = 0; d4 < 16; d4++) {
            float4 v = qr[d4];
            PACK_F32X2(q2[2*d4],   v.x*0.125f, v.y*0.125f);
            PACK_F32X2(q2[2*d4+1], v.z*0.125f, v.w*0.125f);
        }
    }
    ull acc2[32];
    #pragma unroll
    for (int d = 0; d < 32; d++) acc2[d] = 0ull;
    float m = -1e30f, l = 0.f;

    __shared__ float Ks[64][64];
    __shared__ float Vs[64][64];

    const int nkt = 2*qt + 2;          // 64-wide kv tiles covering [0, 128*(qt+1))
    for (int kt = 0; kt < nkt; kt++) {
        __syncthreads();
        const float4* Ksrc = (const float4*)(Kp + (size_t)kt*64*D_);
        const float4* Vsrc = (const float4*)(Vp + (size_t)kt*64*D_);
        for (int u = threadIdx.x; u < 1024; u += 128) {
            ((float4*)Ks)[u] = Ksrc[u];
            ((float4*)Vs)[u] = Vsrc[u];
        }
        __syncthreads();

        const int base = kt*64;
        const bool diag = (base + 63 > i);          // tile crosses my causal edge
        #pragma unroll 1
        for (int j0 = 0; j0 < 64; j0 += 8) {
            // 8 independent QK dots in f32x2
            float s[8];
            #pragma unroll
            for (int c = 0; c < 8; c++) {
                const ulonglong2* kr = (const ulonglong2*)Ks[j0 + c];
                ull d2a = 0ull, d2b = 0ull;
                #pragma unroll
                for (int d4 = 0; d4 < 8; d4++) {
                    ulonglong2 k0 = kr[d4];        // pairs (4d4, 4d4+1)
                    ulonglong2 k1 = kr[d4+8];
                    FMA_F32X2(d2a, q2[2*d4],    k0.x, d2a);
                    FMA_F32X2(d2a, q2[2*d4+1],  k0.y, d2a);
                    FMA_F32X2(d2b, q2[16+2*d4], k1.x, d2b);
                    FMA_F32X2(d2b, q2[17+2*d4], k1.y, d2b);
                }
                float e0,e1,e2,e3;
                UNPACK_F32X2(e0, e1, d2a);
                UNPACK_F32X2(e2, e3, d2b);
                s[c] = (e0 + e1) + (e2 + e3);
            }
            if (diag) {
                #pragma unroll
                for (int c = 0; c < 8; c++)
                    if (base + j0 + c > i) s[c] = -1e30f;
            }
            float cm = s[0];
            #pragma unroll
            for (int c = 1; c < 8; c++) cm = fmaxf(cm, s[c]);
            float mn = fmaxf(m, cm);
            float sc = __expf(m - mn);
            float p[8], ps = 0.f;
            #pragma unroll
            for (int c = 0; c < 8; c++) { p[c] = __expf(s[c] - mn); ps += p[c]; }
            l = l*sc + ps;
            m = mn;
            ull sc2; PACK_F32X2(sc2, sc, sc);
            ull p2[8];
            #pragma unroll
            for (int c = 0; c < 8; c++) PACK_F32X2(p2[c], p[c], p[c]);
            // acc = acc*sc + sum_c p[c] * V[j0+c]   (all f32x2)
            #pragma unroll
            for (int d4 = 0; d4 < 16; d4++) {
                ull a0 = acc2[2*d4], a1 = acc2[2*d4+1];
                MUL_F32X2(a0, a0, sc2);
                MUL_F32X2(a1, a1, sc2);
                #pragma unroll
                for (int c = 0; c < 8; c++) {
                    ulonglong2 vv = ((const ulonglong2*)Vs[j0 + c])[d4];
                    FMA_F32X2(a0, p2[c], vv.x, a0);
                    FMA_F32X2(a1, p2[c], vv.y, a1);
                }
                acc2[2*d4] = a0; acc2[2*d4+1] = a1;
            }
        }
    }

    const float inv = 1.0f / l;
    float* Op = O + (((size_t)(b*T_ + i))*HQ_ + h) * D_;
    #pragma unroll
    for (int d4 = 0; d4 < 16; d4++) {
        float o0,o1,o2,o3;
        UNPACK_F32X2(o0, o1, acc2[2*d4]);
        UNPACK_F32X2(o2, o3, acc2[2*d4+1]);
        ((float4*)Op)[d4] = make_float4(o0*inv, o1*inv, o2*inv, o3*inv);
    }
}

// ---------------------------------------------------------------------------
extern "C" void kernel_launch(void* const* d_in, const int* in_sizes, int n_in,
                              void* d_out, int out_size)
{
    (void)in_sizes; (void)n_in; (void)out_size;
    const float* hidden = (const float*)d_in[0];
    // d_in[1] = positions (always arange(T)), d_in[2] = causal -1e9 mask: both
    // reproduced analytically in-kernel.
    const float* q_w = (const float*)d_in[3];
    const float* q_b = (const float*)d_in[4];
    const float* k_w = (const float*)d_in[5];
    const float* k_b = (const float*)d_in[6];
    const float* v_w = (const float*)d_in[7];
    const float* v_b = (const float*)d_in[8];
    const float* o_w = (const float*)d_in[9];
    float* out = (float*)d_out;

    float *qkv, *Qb, *Kb, *Vb, *attnb;
    cudaGetSymbolAddress((void**)&qkv,   g_QKV);
    cudaGetSymbolAddress((void**)&Qb,    g_Q);
    cudaGetSymbolAddress((void**)&Kb,    g_K);
    cudaGetSymbolAddress((void**)&Vb,    g_V);
    cudaGetSymbolAddress((void**)&attnb, g_attn);

    // fused QKV projection (bias deferred to rope_reshape)
    qkv_gemm<<<dim3(24, 32), 256>>>(hidden, q_w, k_w, v_w, qkv);

    // bias + RoPE + relayout
    rope_reshape<<<M_, 128>>>(qkv, q_b, k_b, v_b, Qb, Kb, Vb);

    // causal GQA attention (128 query rows / block)
    attn_kernel<<<dim3(T_/128, B_*HQ_), 128>>>(Qb, Kb, Vb, attnb);

    // output projection -> d_out
    sgemm_nt<<<dim3(16, 32), 256>>>(attnb, o_w, out, HQ_*D_, HID_);
}

// round 12
// speedup vs baseline: 1.4978x; 1.4978x over previous
#include <cuda_runtime.h>
#include <cuda_bf16.h>
#include <math.h>
#include <cstdint>

#define HQ_  32
#define HKV_ 8
#define D_   64
#define HID_ 2048
#define B_   2
#define T_   2048
#define M_   (B_*T_)          // 4096 rows (B*T)
#define NQKV_ 3072            // 2048 (Q) + 512 (K) + 512 (V)

typedef unsigned long long ull;

// ---------------- packed f32x2 (attention path, validated R4) --------------
#define FMA_F32X2(d, a, b, c) \
    asm("fma.rn.f32x2 %0, %1, %2, %3;" : "=l"(d) : "l"(a), "l"(b), "l"(c))
#define MUL_F32X2(d, a, b) \
    asm("mul.rn.f32x2 %0, %1, %2;" : "=l"(d) : "l"(a), "l"(b))
#define PACK_F32X2(d, lo, hi) \
    asm("mov.b64 %0, {%1, %2};" : "=l"(d) \
        : "r"(__float_as_uint(lo)), "r"(__float_as_uint(hi)))
#define UNPACK_F32X2(lo, hi, s) do {                                   \
    unsigned _u0, _u1;                                                 \
    asm("mov.b64 {%0, %1}, %2;" : "=r"(_u0), "=r"(_u1) : "l"(s));      \
    (lo) = __uint_as_float(_u0); (hi) = __uint_as_float(_u1);          \
} while (0)

// ---------------- plain-target async copy (sm_80+ base features) -----------
#define CP_ASYNC16(saddr, gptr) \
    asm volatile("cp.async.cg.shared.global [%0], [%1], 16;" \
        :: "r"(saddr), "l"(gptr))
#define CP_COMMIT() asm volatile("cp.async.commit_group;" ::: "memory")
#define CP_WAIT1()  asm volatile("cp.async.wait_group 1;" ::: "memory")
#define CP_WAIT0()  asm volatile("cp.async.wait_group 0;" ::: "memory")

__device__ __forceinline__ uint32_t smem_to_u32(const void* p) {
    uint32_t a;
    asm("{ .reg .u64 t; cvta.to.shared.u64 t, %1; cvt.u32.u64 %0, t; }"
        : "=r"(a) : "l"(p));
    return a;
}

// mma.sync m16n8k16 bf16 -> f32 (plain-target tensor core path; compiles at
// compute_103 unlike tcgen05 which requires an 'a' target)
__device__ __forceinline__ void mma16816(float* c, const uint32_t* a, const uint32_t* b)
{
    asm volatile(
        "mma.sync.aligned.m16n8k16.row.col.f32.bf16.bf16.f32 "
        "{%0,%1,%2,%3}, {%4,%5,%6,%7}, {%8,%9}, {%0,%1,%2,%3};"
        : "+f"(c[0]), "+f"(c[1]), "+f"(c[2]), "+f"(c[3])
        : "r"(a[0]), "r"(a[1]), "r"(a[2]), "r"(a[3]), "r"(b[0]), "r"(b[1]));
}

// ---------------- scratch (device globals; no runtime allocation) ----------
__device__ float g_QKV[(size_t)M_ * NQKV_];
__device__ float g_Q[(size_t)B_ * HQ_ * T_ * D_];
__device__ float g_K[(size_t)B_ * HKV_ * T_ * D_];
__device__ float g_V[(size_t)B_ * HKV_ * T_ * D_];
__device__ float g_attn[(size_t)M_ * HQ_ * D_];
// bf16 hi/lo split operands
__device__ __nv_bfloat16 g_hid_h[(size_t)M_ * HID_],  g_hid_l[(size_t)M_ * HID_];
__device__ __nv_bfloat16 g_w_h[(size_t)NQKV_ * HID_], g_w_l[(size_t)NQKV_ * HID_];
__device__ __nv_bfloat16 g_ow_h[(size_t)HID_ * HQ_ * D_], g_ow_l[(size_t)HID_ * HQ_ * D_];
__device__ __nv_bfloat16 g_at_h[(size_t)M_ * HQ_ * D_],  g_at_l[(size_t)M_ * HQ_ * D_];

// ---------------------------------------------------------------------------
// fp32 -> (bf16 hi, bf16 lo) split conversion, 4 elements/thread.
// ---------------------------------------------------------------------------
__global__ __launch_bounds__(256) void cvt_hilo(
    const float* __restrict__ x, __nv_bfloat16* __restrict__ hi,
    __nv_bfloat16* __restrict__ lo, int n4)
{
    int i = blockIdx.x * blockDim.x + threadIdx.x;
    if (i >= n4) return;
    float4 v = ((const float4*)x)[i];
    __nv_bfloat16 h0 = __float2bfloat16(v.x), h1 = __float2bfloat16(v.y);
    __nv_bfloat16 h2 = __float2bfloat16(v.z), h3 = __float2bfloat16(v.w);
    __nv_bfloat16 l0 = __float2bfloat16(v.x - __bfloat162float(h0));
    __nv_bfloat16 l1 = __float2bfloat16(v.y - __bfloat162float(h1));
    __nv_bfloat16 l2 = __float2bfloat16(v.z - __bfloat162float(h2));
    __nv_bfloat16 l3 = __float2bfloat16(v.w - __bfloat162float(h3));
    ((__nv_bfloat162*)hi)[2*i]   = __nv_bfloat162(h0, h1);
    ((__nv_bfloat162*)hi)[2*i+1] = __nv_bfloat162(h2, h3);
    ((__nv_bfloat162*)lo)[2*i]   = __nv_bfloat162(l0, l1);
    ((__nv_bfloat162*)lo)[2*i+1] = __nv_bfloat162(l2, l3);
}

// ---------------------------------------------------------------------------
// Split-bf16 NT GEMM on mma.sync tensor cores.
// C[128x128 tile] = Ahi*Bhi^T + Ahi*Blo^T + Alo*Bhi^T (fp32 accum).
// A_(hi/lo): (M,K) bf16 row-major; B_(hi/lo): (N,K) bf16 row-major. K%32==0.
// 256 threads = 8 warps (2m x 4n), 64x32 per warp, m16n8k16 fragments.
// K staged 32-wide with cp.async double buffering.
// Smem rows padded to 40 bf16 (80B): all fragment LDS are conflict-free.
// ---------------------------------------------------------------------------
#define ROWB 80                        // padded row stride in bytes
#define ARRB (128 * ROWB)              // one operand tile: 10240 B
#define STAGEB (4 * ARRB)              // 4 operand tiles per stage: 40960 B
#define MG_SMEM (2 * STAGEB)           // double buffered: 81920 B

__device__ __forceinline__ void mma_gemm_tile(
    const __nv_bfloat16* __restrict__ Ah, const __nv_bfloat16* __restrict__ Al,
    const __nv_bfloat16* __restrict__ Bh, const __nv_bfloat16* __restrict__ Bl,
    float* __restrict__ C, int K, int ldc, int bm, int bnW, int bnC)
{
    extern __shared__ char dsm[];
    const uint32_t sbase = smem_to_u32(dsm);
    const int tid = threadIdx.x;
    const int wid = tid >> 5, lane = tid & 31;
    const int wm = wid >> 2, wn = wid & 3;     // warp 2x4 grid
    const int g = lane >> 2, tig = lane & 3;   // groupID, thread-in-group

    // per-thread cp.async descriptors: 8 chunks of 16B (2048 chunks/stage)
    const __nv_bfloat16* gsrc[8];
    uint32_t sdst[8];
    #pragma unroll
    for (int i = 0; i < 8; i++) {
        const int id = tid + i * 256;
        const int arr = id >> 9, rem = id & 511;
        const int row = rem >> 2, seg = rem & 3;
        const __nv_bfloat16* base;
        if      (arr == 0) base = Ah + (size_t)(bm  + row) * K;
        else if (arr == 1) base = Al + (size_t)(bm  + row) * K;
        else if (arr == 2) base = Bh + (size_t)(bnW + row) * K;
        else               base = Bl + (size_t)(bnW + row) * K;
        gsrc[i] = base + seg * 8;
        sdst[i] = sbase + arr * ARRB + row * ROWB + seg * 16;
    }

    float acc[4][4][4];
    #pragma unroll
    for (int mt = 0; mt < 4; mt++)
        #pragma unroll
        for (int nt = 0; nt < 4; nt++)
            #pragma unroll
            for (int r = 0; r < 4; r++) acc[mt][nt][r] = 0.f;

    const int S = K >> 5;   // 32-wide stages
    // prologue: stage 0 -> buffer 0
    #pragma unroll
    for (int i = 0; i < 8; i++) CP_ASYNC16(sdst[i], gsrc[i]);
    CP_COMMIT();

    for (int s = 0; s < S; s++) {
        if (s + 1 < S) {
            const uint32_t boff = ((s + 1) & 1) * STAGEB;
            const int k0 = (s + 1) << 5;
            #pragma unroll
            for (int i = 0; i < 8; i++) CP_ASYNC16(sdst[i] + boff, gsrc[i] + k0);
            CP_COMMIT();
            CP_WAIT1();
        } else {
            CP_WAIT0();
        }
        __syncthreads();

        const char* sb = dsm + (s & 1) * STAGEB;
        const char* AHs = sb;
        const char* ALs = sb + ARRB;
        const char* BHs = sb + 2 * ARRB;
        const char* BLs = sb + 3 * ARRB;

        #pragma unroll
        for (int kk = 0; kk < 2; kk++) {       // two k16 halves of the stage
            const int wb = kk * 8;             // word offset within row
            uint32_t ah[4][4], al[4][4], bh[4][2], bl[4][2];
            #pragma unroll
            for (int mt = 0; mt < 4; mt++) {
                const int r0 = wm * 64 + mt * 16 + g;
                const uint32_t o00 = r0 * ROWB + (wb + tig) * 4;
                const uint32_t o10 = (r0 + 8) * ROWB + (wb + tig) * 4;
                ah[mt][0] = *(const uint32_t*)(AHs + o00);
                ah[mt][1] = *(const uint32_t*)(AHs + o10);
                ah[mt][2] = *(const uint32_t*)(AHs + o00 + 16);
                ah[mt][3] = *(const uint32_t*)(AHs + o10 + 16);
                al[mt][0] = *(const uint32_t*)(ALs + o00);
                al[mt][1] = *(const uint32_t*)(ALs + o10);
                al[mt][2] = *(const uint32_t*)(ALs + o00 + 16);
                al[mt][3] = *(const uint32_t*)(ALs + o10 + 16);
            }
            #pragma unroll
            for (int nt = 0; nt < 4; nt++) {
                const int n = wn * 32 + nt * 8 + g;
                const uint32_t o = n * ROWB + (wb + tig) * 4;
                bh[nt][0] = *(const uint32_t*)(BHs + o);
                bh[nt][1] = *(const uint32_t*)(BHs + o + 16);
                bl[nt][0] = *(const uint32_t*)(BLs + o);
                bl[nt][1] = *(const uint32_t*)(BLs + o + 16);
            }
            #pragma unroll
            for (int mt = 0; mt < 4; mt++)
                #pragma unroll
                for (int nt = 0; nt < 4; nt++) {
                    mma16816(acc[mt][nt], ah[mt], bh[nt]);
                    mma16816(acc[mt][nt], ah[mt], bl[nt]);
                    mma16816(acc[mt][nt], al[mt], bh[nt]);
                }
        }
        __syncthreads();
    }

    // epilogue: c0/c1 row g, c2/c3 row g+8; cols tig*2, tig*2+1 (contiguous)
    #pragma unroll
    for (int mt = 0; mt < 4; mt++) {
        const int r0 = bm + wm * 64 + mt * 16 + g;
        #pragma unroll
        for (int nt = 0; nt < 4; nt++) {
            float* cp = C + (size_t)r0 * ldc + bnC + wn * 32 + nt * 8 + tig * 2;
            *(float2*)cp = make_float2(acc[mt][nt][0], acc[mt][nt][1]);
            *(float2*)(cp + (size_t)8 * ldc) = make_float2(acc[mt][nt][2], acc[mt][nt][3]);
        }
    }
}

// Fused QKV projection: one launch covers Q (cols 0..2047), K (2048..2559),
// V (2560..3071); the weight tensor is selected per-block from bn.
__global__ __launch_bounds__(256) void qkv_gemm(
    const __nv_bfloat16* __restrict__ hidh, const __nv_bfloat16* __restrict__ hidl,
    const __nv_bfloat16* __restrict__ wh,   const __nv_bfloat16* __restrict__ wl,
    float* __restrict__ C)
{
    // wh/wl hold q rows [0,2048), k rows [2048,2560), v rows [2560,3072)
    const int bn = blockIdx.x * 128;
    mma_gemm_tile(hidh, hidl, wh, wl, C, HID_, NQKV_, blockIdx.y * 128, bn, bn);
}

__global__ __launch_bounds__(256) void o_gemm(
    const __nv_bfloat16* __restrict__ ah, const __nv_bfloat16* __restrict__ al,
    const __nv_bfloat16* __restrict__ wh, const __nv_bfloat16* __restrict__ wl,
    float* __restrict__ C)
{
    mma_gemm_tile(ah, al, wh, wl, C, HQ_ * D_, HID_,
                  blockIdx.y * 128, blockIdx.x * 128, blockIdx.x * 128);
}

// ---------------------------------------------------------------------------
// Bias add + RoPE + layout transform (unchanged, validated).
// ---------------------------------------------------------------------------
__global__ __launch_bounds__(128) void rope_reshape(
    const float* __restrict__ qkv,
    const float* __restrict__ qb, const float* __restrict__ kb,
    const float* __restrict__ vb,
    float* __restrict__ Q, float* __restrict__ K, float* __restrict__ V)
{
    const int bt = blockIdx.x;
    const int b = bt / T_, t = bt % T_;
    const float* row = qkv + (size_t)bt * NQKV_;
    const float pos = (float)t;
    const float LOG_TH_OVER_HALF = 9.210340371976184f / 32.0f;

    for (int it = threadIdx.x; it < HQ_*32; it += blockDim.x) {
        int h = it >> 5, j = it & 31;
        float invf = expf(-(float)j * LOG_TH_OVER_HALF);
        float sn, cs; sincosf(pos * invf, &sn, &cs);
        float x1 = row[h*64 + j]      + qb[h*64 + j];
        float x2 = row[h*64 + j + 32] + qb[h*64 + j + 32];
        float* o = Q + (((size_t)b*HQ_ + h)*T_ + t)*64;
        o[j]      = x1*cs - x2*sn;
        o[j + 32] = x2*cs + x1*sn;
    }
    for (int it = threadIdx.x; it < HKV_*32; it += blockDim.x) {
        int h = it >> 5, j = it & 31;
        float invf = expf(-(float)j * LOG_TH_OVER_HALF);
        float sn, cs; sincosf(pos * invf, &sn, &cs);
        float x1 = row[2048 + h*64 + j]      + kb[h*64 + j];
        float x2 = row[2048 + h*64 + j + 32] + kb[h*64 + j + 32];
        float* o = K + (((size_t)b*HKV_ + h)*T_ + t)*64;
        o[j]      = x1*cs - x2*sn;
        o[j + 32] = x2*cs + x1*sn;
    }
    for (int it = threadIdx.x; it < HKV_*64; it += blockDim.x) {
        V[(((size_t)b*HKV_ + (it >> 6))*T_ + t)*64 + (it & 63)] =
            row[2560 + it] + vb[it];
    }
}

// ---------------------------------------------------------------------------
// Flash-style causal GQA attention in packed f32x2 (unchanged, validated).
// ---------------------------------------------------------------------------
__global__ __launch_bounds__(128) void attn_kernel(
    const float* __restrict__ Q, const float* __restrict__ K,
    const float* __restrict__ V, float* __restrict__ O)
{
    const int qt = (gridDim.x - 1) - blockIdx.x;
    const int bh = blockIdx.y;
    const int b = bh / HQ_, h = bh % HQ_;
    const int kvh = h / (HQ_ / HKV_);
    const float* Qp = Q + (((size_t)b*HQ_  + h  )*T_) * D_;
    const float* Kp = K + (((size_t)b*HKV_ + kvh)*T_) * D_;
    const float* Vp = V + (((size_t)b*HKV_ + kvh)*T_) * D_;
    const int i = qt*128 + threadIdx.x;

    ull q2[32];
    {
        const float4* qr = (const float4*)(Qp + (size_t)i * D_);
        #pragma unroll
        for (int d4 = 0; d4 < 16; d4++) {
            float4 v = qr[d4];
            PACK_F32X2(q2[2*d4],   v.x*0.125f, v.y*0.125f);
            PACK_F32X2(q2[2*d4+1], v.z*0.125f, v.w*0.125f);
        }
    }
    ull acc2[32];
    #pragma unroll
    for (int d = 0; d < 32; d++) acc2[d] = 0ull;
    float m = -1e30f, l = 0.f;

    __shared__ float Ks[64][64];
    __shared__ float Vs[64][64];

    const int nkt = 2*qt + 2;
    for (int kt = 0; kt < nkt; kt++) {
        __syncthreads();
        const float4* Ksrc = (const float4*)(Kp + (size_t)kt*64*D_);
        const float4* Vsrc = (const float4*)(Vp + (size_t)kt*64*D_);
        for (int u = threadIdx.x; u < 1024; u += 128) {
            ((float4*)Ks)[u] = Ksrc[u];
            ((float4*)Vs)[u] = Vsrc[u];
        }
        __syncthreads();

        const int base = kt*64;
        const bool diag = (base + 63 > i);
        #pragma unroll 1
        for (int j0 = 0; j0 < 64; j0 += 8) {
            float s[8];
            #pragma unroll
            for (int c = 0; c < 8; c++) {
                const ulonglong2* kr = (const ulonglong2*)Ks[j0 + c];
                ull d2a = 0ull, d2b = 0ull;
                #pragma unroll
                for (int d4 = 0; d4 < 8; d4++) {
                    ulonglong2 k0 = kr[d4];
                    ulonglong2 k1 = kr[d4+8];
                    FMA_F32X2(d2a, q2[2*d4],    k0.x, d2a);
                    FMA_F32X2(d2a, q2[2*d4+1],  k0.y, d2a);
                    FMA_F32X2(d2b, q2[16+2*d4], k1.x, d2b);
                    FMA_F32X2(d2b, q2[17+2*d4], k1.y, d2b);
                }
                float e0,e1,e2,e3;
                UNPACK_F32X2(e0, e1, d2a);
                UNPACK_F32X2(e2, e3, d2b);
                s[c] = (e0 + e1) + (e2 + e3);
            }
            if (diag) {
                #pragma unroll
                for (int c = 0; c < 8; c++)
                    if (base + j0 + c > i) s[c] = -1e30f;
            }
            float cm = s[0];
            #pragma unroll
            for (int c = 1; c < 8; c++) cm = fmaxf(cm, s[c]);
            float mn = fmaxf(m, cm);
            float sc = __expf(m - mn);
            float p[8], ps = 0.f;
            #pragma unroll
            for (int c = 0; c < 8; c++) { p[c] = __expf(s[c] - mn); ps += p[c]; }
            l = l*sc + ps;
            m = mn;
            ull sc2; PACK_F32X2(sc2, sc, sc);
            ull p2[8];
            #pragma unroll
            for (int c = 0; c < 8; c++) PACK_F32X2(p2[c], p[c], p[c]);
            #pragma unroll
            for (int d4 = 0; d4 < 16; d4++) {
                ull a0 = acc2[2*d4], a1 = acc2[2*d4+1];
                MUL_F32X2(a0, a0, sc2);
                MUL_F32X2(a1, a1, sc2);
                #pragma unroll
                for (int c = 0; c < 8; c++) {
                    ulonglong2 vv = ((const ulonglong2*)Vs[j0 + c])[d4];
                    FMA_F32X2(a0, p2[c], vv.x, a0);
                    FMA_F32X2(a1, p2[c], vv.y, a1);
                }
                acc2[2*d4] = a0; acc2[2*d4+1] = a1;
            }
        }
    }

    const float inv = 1.0f / l;
    float* Op = O + (((size_t)(b*T_ + i))*HQ_ + h) * D_;
    #pragma unroll
    for (int d4 = 0; d4 < 16; d4++) {
        float o0,o1,o2,o3;
        UNPACK_F32X2(o0, o1, acc2[2*d4]);
        UNPACK_F32X2(o2, o3, acc2[2*d4+1]);
        ((float4*)Op)[d4] = make_float4(o0*inv, o1*inv, o2*inv, o3*inv);
    }
}

// ---------------------------------------------------------------------------
extern "C" void kernel_launch(void* const* d_in, const int* in_sizes, int n_in,
                              void* d_out, int out_size)
{
    (void)in_sizes; (void)n_in; (void)out_size;
    const float* hidden = (const float*)d_in[0];
    const float* q_w = (const float*)d_in[3];
    const float* q_b = (const float*)d_in[4];
    const float* k_w = (const float*)d_in[5];
    const float* k_b = (const float*)d_in[6];
    const float* v_w = (const float*)d_in[7];
    const float* v_b = (const float*)d_in[8];
    const float* o_w = (const float*)d_in[9];
    float* out = (float*)d_out;

    float *qkv, *Qb, *Kb, *Vb, *attnb;
    cudaGetSymbolAddress((void**)&qkv,   g_QKV);
    cudaGetSymbolAddress((void**)&Qb,    g_Q);
    cudaGetSymbolAddress((void**)&Kb,    g_K);
    cudaGetSymbolAddress((void**)&Vb,    g_V);
    cudaGetSymbolAddress((void**)&attnb, g_attn);
    __nv_bfloat16 *hidh, *hidl, *wh, *wl, *owh, *owl, *ath, *atl;
    cudaGetSymbolAddress((void**)&hidh, g_hid_h);
    cudaGetSymbolAddress((void**)&hidl, g_hid_l);
    cudaGetSymbolAddress((void**)&wh,   g_w_h);
    cudaGetSymbolAddress((void**)&wl,   g_w_l);
    cudaGetSymbolAddress((void**)&owh,  g_ow_h);
    cudaGetSymbolAddress((void**)&owl,  g_ow_l);
    cudaGetSymbolAddress((void**)&ath,  g_at_h);
    cudaGetSymbolAddress((void**)&atl,  g_at_l);

    cudaFuncSetAttribute(qkv_gemm, cudaFuncAttributeMaxDynamicSharedMemorySize, MG_SMEM);
    cudaFuncSetAttribute(o_gemm,   cudaFuncAttributeMaxDynamicSharedMemorySize, MG_SMEM);

    // hi/lo split conversions (QKV weights concatenated: q rows 0.., k 2048.., v 2560..)
    {
        int n4;
        n4 = (M_*HID_)/4;       cvt_hilo<<<(n4+255)/256, 256>>>(hidden, hidh, hidl, n4);
        n4 = (2048*HID_)/4;     cvt_hilo<<<(n4+255)/256, 256>>>(q_w, wh, wl, n4);
        n4 = (512*HID_)/4;      cvt_hilo<<<(n4+255)/256, 256>>>(k_w, wh + (size_t)2048*HID_, wl + (size_t)2048*HID_, n4);
        n4 = (512*HID_)/4;      cvt_hilo<<<(n4+255)/256, 256>>>(v_w, wh + (size_t)2560*HID_, wl + (size_t)2560*HID_, n4);
        n4 = (HID_*HQ_*D_)/4;   cvt_hilo<<<(n4+255)/256, 256>>>(o_w, owh, owl, n4);
    }

    // QKV projection on tensor cores (bias deferred to rope_reshape)
    qkv_gemm<<<dim3(NQKV_/128, M_/128), 256, MG_SMEM>>>(hidh, hidl, wh, wl, qkv);

    // bias + RoPE + relayout
    rope_reshape<<<M_, 128>>>(qkv, q_b, k_b, v_b, Qb, Kb, Vb);

    // causal GQA attention
    attn_kernel<<<dim3(T_/128, B_*HQ_), 128>>>(Qb, Kb, Vb, attnb);

    // output projection on tensor cores
    {
        int n4 = (M_*HQ_*D_)/4;
        cvt_hilo<<<(n4+255)/256, 256>>>(attnb, ath, atl, n4);
    }
    o_gemm<<<dim3(HID_/128, M_/128), 256, MG_SMEM>>>(ath, atl, owh, owl, out);
}